// round 1
// baseline (speedup 1.0000x reference)
#include <cuda_runtime.h>

// LUT tree: x (B,1024) -> layer tables t0(256,16) t1(64,16) t2(16,16) t3(4,16) t4(1,16) -> out (B,)
// One warp per row. Lane l computes layer-0 nodes {32j + l}, j=0..7 (coalesced
// float4 x loads AND conflict-free padded shared-table reads). Layer0->1 via a
// small shared exchange; layers 2..4 via warp shuffles.

#define ROWS_PER_BLOCK 8
#define THREADS 256

// padded table layout in shared: 20 floats per node (16 used + 4 pad)
// -> 80B node stride -> LDS.128 lane stride of 5 16B-units -> conflict-free
#define TPAD 20
#define OFF0 0
#define OFF1 (256 * TPAD)            // 5120
#define OFF2 (OFF1 + 64 * TPAD)      // 6400
#define OFF3 (OFF2 + 16 * TPAD)      // 6720
#define OFF4 (OFF3 + 4 * TPAD)       // 6800
#define TTOT (OFF4 + TPAD)           // 6820

__device__ __forceinline__ float lerpf(float a, float b, float x) {
    return fmaf(x, b - a, a);
}

// 4D multilinear interpolation: 16 corners at t[0..15], inputs xv.{x,y,z,w}
// corner index c: bit i of c corresponds to x_i  =>  collapse bit0 first.
__device__ __forceinline__ float node_eval(const float* t, float4 xv) {
    float4 c0 = *(const float4*)(t + 0);
    float4 c1 = *(const float4*)(t + 4);
    float4 c2 = *(const float4*)(t + 8);
    float4 c3 = *(const float4*)(t + 12);
    float v0 = lerpf(c0.x, c0.y, xv.x);
    float v1 = lerpf(c0.z, c0.w, xv.x);
    float v2 = lerpf(c1.x, c1.y, xv.x);
    float v3 = lerpf(c1.z, c1.w, xv.x);
    float v4 = lerpf(c2.x, c2.y, xv.x);
    float v5 = lerpf(c2.z, c2.w, xv.x);
    float v6 = lerpf(c3.x, c3.y, xv.x);
    float v7 = lerpf(c3.z, c3.w, xv.x);
    float w0 = lerpf(v0, v1, xv.y);
    float w1 = lerpf(v2, v3, xv.y);
    float w2 = lerpf(v4, v5, xv.y);
    float w3 = lerpf(v6, v7, xv.y);
    float z0 = lerpf(w0, w1, xv.z);
    float z1 = lerpf(w2, w3, xv.z);
    return lerpf(z0, z1, xv.w);
}

__global__ void __launch_bounds__(THREADS) lut_tree_kernel(
    const float* __restrict__ x,
    const float* __restrict__ t0, const float* __restrict__ t1,
    const float* __restrict__ t2, const float* __restrict__ t3,
    const float* __restrict__ t4,
    float* __restrict__ out, int n_rows)
{
    __shared__ __align__(16) float sh_t[TTOT];
    __shared__ __align__(16) float sh_x[ROWS_PER_BLOCK][256];

    // cooperative padded table load
    {
        const float* tabs[5] = {t0, t1, t2, t3, t4};
        const int nn[5] = {256, 64, 16, 4, 1};
        int off = 0;
        #pragma unroll
        for (int L = 0; L < 5; ++L) {
            int n = nn[L] * 16;
            for (int e = threadIdx.x; e < n; e += THREADS)
                sh_t[off + (e >> 4) * TPAD + (e & 15)] = tabs[L][e];
            off += nn[L] * TPAD;
        }
    }
    __syncthreads();

    const int warp = threadIdx.x >> 5;
    const int lane = threadIdx.x & 31;
    const int row = blockIdx.x * ROWS_PER_BLOCK + warp;
    if (row >= n_rows) return;

    // ---- load x row: 8 coalesced float4 warp loads ----
    const float4* xr = (const float4*)(x + (size_t)row * 1024);
    float4 X[8];
    #pragma unroll
    for (int j = 0; j < 8; ++j) X[j] = xr[j * 32 + lane];

    // ---- layer 0: 256 nodes; lane computes nodes 32j+lane ----
    float y[8];
    #pragma unroll
    for (int j = 0; j < 8; ++j) {
        int n = j * 32 + lane;
        y[j] = node_eval(&sh_t[OFF0 + n * TPAD], X[j]);
    }

    // exchange (output index 32j+lane -> position 32j+lane)
    float* xch = &sh_x[warp][0];
    #pragma unroll
    for (int j = 0; j < 8; ++j) xch[j * 32 + lane] = y[j];
    __syncwarp();

    // ---- layer 1: 64 nodes; lane computes nodes 2*lane, 2*lane+1 ----
    float4 a0 = *(const float4*)&xch[lane * 8];
    float4 a1 = *(const float4*)&xch[lane * 8 + 4];
    float z0 = node_eval(&sh_t[OFF1 + (2 * lane) * TPAD], a0);
    float z1 = node_eval(&sh_t[OFF1 + (2 * lane + 1) * TPAD], a1);

    const unsigned FULL = 0xffffffffu;

    // ---- layer 2: 16 nodes; lane l<16 computes node l ----
    // node l inputs = layer1 outputs 4l..4l+3 = {z0,z1}@lane 2l, {z0,z1}@lane 2l+1
    float4 b;
    b.x = __shfl_sync(FULL, z0, (lane * 2) & 31);
    b.y = __shfl_sync(FULL, z1, (lane * 2) & 31);
    b.z = __shfl_sync(FULL, z0, (lane * 2 + 1) & 31);
    b.w = __shfl_sync(FULL, z1, (lane * 2 + 1) & 31);
    float w = node_eval(&sh_t[OFF2 + (lane & 15) * TPAD], b);

    // ---- layer 3: 4 nodes; lane l<4 computes node l ----
    float4 c;
    c.x = __shfl_sync(FULL, w, (lane * 4 + 0) & 31);
    c.y = __shfl_sync(FULL, w, (lane * 4 + 1) & 31);
    c.z = __shfl_sync(FULL, w, (lane * 4 + 2) & 31);
    c.w = __shfl_sync(FULL, w, (lane * 4 + 3) & 31);
    float v = node_eval(&sh_t[OFF3 + (lane & 3) * TPAD], c);

    // ---- layer 4: 1 node from lanes 0..3 ----
    float4 d;
    d.x = __shfl_sync(FULL, v, 0);
    d.y = __shfl_sync(FULL, v, 1);
    d.z = __shfl_sync(FULL, v, 2);
    d.w = __shfl_sync(FULL, v, 3);
    if (lane == 0) out[row] = node_eval(&sh_t[OFF4], d);
}

extern "C" void kernel_launch(void* const* d_in, const int* in_sizes, int n_in,
                              void* d_out, int out_size) {
    const float* x  = (const float*)d_in[0];
    const float* t0 = (const float*)d_in[1];
    const float* t1 = (const float*)d_in[2];
    const float* t2 = (const float*)d_in[3];
    const float* t3 = (const float*)d_in[4];
    const float* t4 = (const float*)d_in[5];
    float* out = (float*)d_out;

    int n_rows = in_sizes[0] / 1024;  // 32768
    int grid = (n_rows + ROWS_PER_BLOCK - 1) / ROWS_PER_BLOCK;
    lut_tree_kernel<<<grid, THREADS>>>(x, t0, t1, t2, t3, t4, out, n_rows);
}

// round 2
// speedup vs baseline: 1.5952x; 1.5952x over previous
#include <cuda_runtime.h>

// LUT tree: x (B,1024) -> t0(256,16) t1(64,16) t2(16,16) t3(4,16) t4(1,16) -> out (B,)
// G=4 rows per warp; lane l handles layer-0 nodes {32j+l}. Table regs loaded once
// per node-group j and reused across the 4 rows (4x less LDS table traffic).
// Tables stored in shared PRE-DIFFERENCED: (a, b-a) pairs -> first lerp level is
// a single FFMA. Layer0->1 via per-warp shared exchange; layers 2..4 via shuffles.

#define G       4      // rows per warp
#define NWARPS  8
#define THREADS (NWARPS * 32)

// padded table layout: 20 floats per node (16 used + 4 pad) -> 80B stride,
// conflict-free LDS.128 across lanes
#define TPAD 20
#define OFF0 0
#define OFF1 (256 * TPAD)
#define OFF2 (OFF1 + 64 * TPAD)
#define OFF3 (OFF2 + 16 * TPAD)
#define OFF4 (OFF3 + 4 * TPAD)
#define TTOT (OFF4 + TPAD)                 // 6820 floats
#define XCHF (NWARPS * G * 256)            // exchange floats
#define SMEM_BYTES ((TTOT + XCHF) * 4)     // 60048 B

__device__ __forceinline__ float lerpf(float a, float b, float x) {
    return fmaf(x, b - a, a);
}

// tables are pre-differenced: t = (a0,d0,a1,d1,...,a7,d7), d_k = corner(2k+1)-corner(2k)
__device__ __forceinline__ float node_eval_pd(float4 c0, float4 c1, float4 c2, float4 c3,
                                              float4 xv) {
    float v0 = fmaf(xv.x, c0.y, c0.x);
    float v1 = fmaf(xv.x, c0.w, c0.z);
    float v2 = fmaf(xv.x, c1.y, c1.x);
    float v3 = fmaf(xv.x, c1.w, c1.z);
    float v4 = fmaf(xv.x, c2.y, c2.x);
    float v5 = fmaf(xv.x, c2.w, c2.z);
    float v6 = fmaf(xv.x, c3.y, c3.x);
    float v7 = fmaf(xv.x, c3.w, c3.z);
    float w0 = lerpf(v0, v1, xv.y);
    float w1 = lerpf(v2, v3, xv.y);
    float w2 = lerpf(v4, v5, xv.y);
    float w3 = lerpf(v6, v7, xv.y);
    float z0 = lerpf(w0, w1, xv.z);
    float z1 = lerpf(w2, w3, xv.z);
    return lerpf(z0, z1, xv.w);
}

__device__ __forceinline__ float node_eval_sh(const float* t, float4 xv) {
    float4 c0 = *(const float4*)(t + 0);
    float4 c1 = *(const float4*)(t + 4);
    float4 c2 = *(const float4*)(t + 8);
    float4 c3 = *(const float4*)(t + 12);
    return node_eval_pd(c0, c1, c2, c3, xv);
}

__global__ void __launch_bounds__(THREADS) lut_tree_kernel(
    const float* __restrict__ x,
    const float* __restrict__ t0, const float* __restrict__ t1,
    const float* __restrict__ t2, const float* __restrict__ t3,
    const float* __restrict__ t4,
    float* __restrict__ out, int n_rows)
{
    extern __shared__ __align__(16) float smem[];
    float* sh_t = smem;            // TTOT floats, pre-differenced padded tables
    float* sh_x = smem + TTOT;     // [NWARPS][G][256] exchange

    // cooperative pre-differenced table load: element pairs (a, b-a)
    {
        const float* tabs[5] = {t0, t1, t2, t3, t4};
        const int nn[5] = {256, 64, 16, 4, 1};
        int off = 0;
        #pragma unroll
        for (int L = 0; L < 5; ++L) {
            int npairs = nn[L] * 8;
            for (int p = threadIdx.x; p < npairs; p += THREADS) {
                int node = p >> 3, k = p & 7;
                float a = tabs[L][node * 16 + 2 * k];
                float b = tabs[L][node * 16 + 2 * k + 1];
                sh_t[off + node * TPAD + 2 * k]     = a;
                sh_t[off + node * TPAD + 2 * k + 1] = b - a;
            }
            off += nn[L] * TPAD;
        }
    }
    __syncthreads();

    const int warp = threadIdx.x >> 5;
    const int lane = threadIdx.x & 31;
    const int row0 = (blockIdx.x * NWARPS + warp) * G;   // grid sized exactly

    float* xch = sh_x + warp * (G * 256);

    // ---- layer 0: j-outer so table regs are reused across G rows ----
    #pragma unroll
    for (int j = 0; j < 8; ++j) {
        float4 Xr[G];
        #pragma unroll
        for (int r = 0; r < G; ++r)
            Xr[r] = ((const float4*)(x + (size_t)(row0 + r) * 1024))[j * 32 + lane];

        const float* tp = &sh_t[OFF0 + (j * 32 + lane) * TPAD];
        float4 c0 = *(const float4*)(tp + 0);
        float4 c1 = *(const float4*)(tp + 4);
        float4 c2 = *(const float4*)(tp + 8);
        float4 c3 = *(const float4*)(tp + 12);

        #pragma unroll
        for (int r = 0; r < G; ++r)
            xch[r * 256 + j * 32 + lane] = node_eval_pd(c0, c1, c2, c3, Xr[r]);
    }
    __syncwarp();

    const unsigned FULL = 0xffffffffu;

    // ---- layers 1..4 per row ----
    #pragma unroll
    for (int r = 0; r < G; ++r) {
        // layer 1: 64 nodes; lane computes nodes 2*lane, 2*lane+1
        float4 a0 = *(const float4*)&xch[r * 256 + lane * 8];
        float4 a1 = *(const float4*)&xch[r * 256 + lane * 8 + 4];
        float z0 = node_eval_sh(&sh_t[OFF1 + (2 * lane) * TPAD], a0);
        float z1 = node_eval_sh(&sh_t[OFF1 + (2 * lane + 1) * TPAD], a1);

        // layer 2: 16 nodes; lane l (mod 16) computes node l
        float4 b;
        b.x = __shfl_sync(FULL, z0, (lane * 2) & 31);
        b.y = __shfl_sync(FULL, z1, (lane * 2) & 31);
        b.z = __shfl_sync(FULL, z0, (lane * 2 + 1) & 31);
        b.w = __shfl_sync(FULL, z1, (lane * 2 + 1) & 31);
        float w = node_eval_sh(&sh_t[OFF2 + (lane & 15) * TPAD], b);

        // layer 3: 4 nodes
        float4 c;
        c.x = __shfl_sync(FULL, w, (lane * 4 + 0) & 31);
        c.y = __shfl_sync(FULL, w, (lane * 4 + 1) & 31);
        c.z = __shfl_sync(FULL, w, (lane * 4 + 2) & 31);
        c.w = __shfl_sync(FULL, w, (lane * 4 + 3) & 31);
        float v = node_eval_sh(&sh_t[OFF3 + (lane & 3) * TPAD], c);

        // layer 4: 1 node from lanes 0..3
        float4 d;
        d.x = __shfl_sync(FULL, v, 0);
        d.y = __shfl_sync(FULL, v, 1);
        d.z = __shfl_sync(FULL, v, 2);
        d.w = __shfl_sync(FULL, v, 3);
        if (lane == 0 && row0 + r < n_rows)
            out[row0 + r] = node_eval_sh(&sh_t[OFF4], d);
    }
}

extern "C" void kernel_launch(void* const* d_in, const int* in_sizes, int n_in,
                              void* d_out, int out_size) {
    const float* x  = (const float*)d_in[0];
    const float* t0 = (const float*)d_in[1];
    const float* t1 = (const float*)d_in[2];
    const float* t2 = (const float*)d_in[3];
    const float* t3 = (const float*)d_in[4];
    const float* t4 = (const float*)d_in[5];
    float* out = (float*)d_out;

    int n_rows = in_sizes[0] / 1024;                 // 32768
    int rows_per_block = NWARPS * G;                 // 32
    int grid = (n_rows + rows_per_block - 1) / rows_per_block;

    cudaFuncSetAttribute(lut_tree_kernel,
                         cudaFuncAttributeMaxDynamicSharedMemorySize, SMEM_BYTES);
    lut_tree_kernel<<<grid, THREADS, SMEM_BYTES>>>(x, t0, t1, t2, t3, t4, out, n_rows);
}